// round 8
// baseline (speedup 1.0000x reference)
#include <cuda_runtime.h>

// CapsuleLayer: x[8,2048,512], W[32,512,64] -> nodes[8,32,64]
// Fused routing, capsules never materialized:
//   nodes = (sum_s r*x) @ W[n];  agreement = x . (W[n] @ tanh(nodes))

#define BB 8
#define SS 2048
#define II 512
#define NN 32
#define DD 64
#define TS 64            // s-rows per fused block
#define NTB 32           // fused blocks per b (yP slabs)
#define PP2 128          // xsum partial slabs
#define SPS 34           // sP row stride (floats, padded)
#define SPSPLIT (TS*SPS) // 2176 floats per K-split

typedef unsigned long long ull;

__device__ __align__(16) float g_xsumP[PP2*BB*II];      // 2MB
__device__ __align__(16) float g_yP[BB*NN*NTB*II];      // 16MB per-block y partials
__device__ __align__(16) float g_U[BB*II*NN];           // [b][i>>2][n][i&3]
__device__ __align__(16) float g_t[BB*NN*DD];           // tanh(nodes)
__device__ float g_b1[BB*SS*NN];

__device__ __forceinline__ void ffma2(ull &d, ull a, ull b){
    asm("fma.rn.f32x2 %0, %1, %2, %0;" : "+l"(d) : "l"(a), "l"(b));
}
__device__ __forceinline__ ull pack2(float lo, float hi){
    ull r; asm("mov.b64 %0, {%1, %2};" : "=l"(r) : "f"(lo), "f"(hi)); return r;
}
__device__ __forceinline__ float2 unpack2(ull v){
    float2 r; asm("mov.b64 {%0, %1}, %2;" : "=f"(r.x), "=f"(r.y) : "l"(v)); return r;
}

// ------------------------------------------------ xsum partials (float4, no atomics)
__global__ void xsum_kernel(const float* __restrict__ x){
    int p = blockIdx.x, b = blockIdx.y, tid = threadIdx.x;   // grid (32,8), 512 thr
    int c4 = tid & 127, rq = tid >> 7;
    const float4* xp = (const float4*)(x + ((size_t)(b*SS + p*64 + rq*16))*II) + c4;
    float4 a = {0.f,0.f,0.f,0.f};
    #pragma unroll
    for (int r = 0; r < 16; r++){
        float4 v = xp[(size_t)r*(II/4)];
        a.x += v.x; a.y += v.y; a.z += v.z; a.w += v.w;
    }
    *(float4*)&g_xsumP[(size_t)((p*4 + rq)*BB + b)*II + c4*4] = a;
}

// ------------------------------------------------ nodes part A: reduce y + GEMV
// grid (NN, BB), 512 threads. out!=null => final iter: write nodes; else g_t.
__global__ void __launch_bounds__(512)
nodesA_kernel(const float* __restrict__ W, float scale,
              int use_xsum, float* __restrict__ out){
    int n = blockIdx.x, b = blockIdx.y, tid = threadIdx.x;
    __shared__ float ys[II];
    __shared__ float sPart[32*68];   // padded stride 68

    if (tid < II){
        float a = 0.f;
        if (use_xsum){
            const float* p0 = g_xsumP + tid;
            #pragma unroll 16
            for (int p = 0; p < PP2; p++) a += p0[(size_t)(p*BB + b)*II];
        } else {
            const float* p0 = g_yP + ((size_t)(b*NN + n)*NTB)*II + tid;
            #pragma unroll
            for (int t = 0; t < NTB; t++) a += p0[(size_t)t*II];
        }
        ys[tid] = a;
    }
    __syncthreads();

    {
        int d4 = tid & 15, ch = tid >> 4;           // 16 d-quads x 32 i-chunks
        const float4* Wp = (const float4*)(W + ((size_t)n*II + ch*16)*DD) + d4;
        float4 acc = {0.f,0.f,0.f,0.f};
        #pragma unroll
        for (int j = 0; j < 16; j++){
            float yv = ys[ch*16 + j];
            float4 w = Wp[j*16];
            acc.x += yv*w.x; acc.y += yv*w.y; acc.z += yv*w.z; acc.w += yv*w.w;
        }
        float* sp = &sPart[ch*68 + d4*4];
        sp[0] = acc.x; sp[1] = acc.y; sp[2] = acc.z; sp[3] = acc.w;
    }
    __syncthreads();
    if (tid < DD){
        float nd = 0.f;
        #pragma unroll
        for (int ch = 0; ch < 32; ch++) nd += sPart[ch*68 + tid];
        nd *= scale;
        if (out) out[(size_t)(b*NN + n)*DD + tid] = nd;
        else     g_t[(size_t)(b*NN + n)*DD + tid] = tanhf(nd);
    }
}

// ------------------------------------------------ nodes part B: U = W[n] @ tanh
// grid (NN, 4, BB), 128 threads; one i per thread.
__global__ void __launch_bounds__(128)
nodesB_kernel(const float* __restrict__ W){
    int n = blockIdx.x, ic = blockIdx.y, b = blockIdx.z, tid = threadIdx.x;
    __shared__ float tsm[DD];
    if (tid < DD) tsm[tid] = g_t[(size_t)(b*NN + n)*DD + tid];
    __syncthreads();
    int i = ic*128 + tid;
    const float4* Wr = (const float4*)(W + ((size_t)n*II + i)*DD);
    float acc = 0.f;
    #pragma unroll
    for (int d4 = 0; d4 < 16; d4++){
        float4 w = Wr[d4];
        acc += w.x*tsm[4*d4] + w.y*tsm[4*d4+1] + w.z*tsm[4*d4+2] + w.w*tsm[4*d4+3];
    }
    g_U[(size_t)b*(II*NN) + (size_t)(i>>2)*(NN*4) + n*4 + (i&3)] = acc;
}

// ------------------------------------------------ fused routing pass
// phase1: register-tiled X@U (warp = 32r x 16n, K/4 per warp) -> softmax -> phase2 y
// grid (NTB, BB), 512 threads, 231KB smem.
__global__ void __launch_bounds__(512, 1)
fused_pass_kernel(const float* __restrict__ x, int pass_c){
    extern __shared__ float smem[];
    float* sX = smem;                 // TS*II = 32768 floats (128KB)
    float* sU = sX + TS*II;           // II*NN = 16384 floats (64KB, quad layout)
    float* sP = sU + II*NN;           // 4*SPSPLIT = 8704 floats (34KB, padded)
    float* sR = sP;                   // aliases sP (guarded by barriers)
    int blk = blockIdx.x, b = blockIdx.y, tid = threadIdx.x;
    int w = tid >> 5, lane = tid & 31;
    int s0 = blk*TS;

    // ---- stage x tile + U (coalesced float4)
    const float4* xt = (const float4*)(x + ((size_t)(b*SS + s0))*II);
    #pragma unroll
    for (int it = 0; it < TS*II/4/512; it++)
        ((float4*)sX)[it*512 + tid] = xt[it*512 + tid];
    const float4* Ub = (const float4*)(g_U + (size_t)b*(II*NN));
    #pragma unroll
    for (int it = 0; it < II*NN/4/512; it++)
        ((float4*)sU)[it*512 + tid] = Ub[it*512 + tid];
    __syncthreads();

    // ---- phase 1a: register-tiled agreement
    // warp w: ks=w&3 (K-slice of 32 q), nt=(w>>2)&1 (16 n), rt=w>>3 (32 rows)
    // thread: tr=lane>>1 (2 rows), tn=lane&1 (8 n)
    {
        int ks = w & 3, nt = (w >> 2) & 1, rt = w >> 3;
        int tr = lane >> 1, tn = lane & 1;
        int r0 = rt*32 + tr*2;
        int nb0 = nt*16 + tn*8;
        int q0 = ks*32;
        ull acc[2][8];
        #pragma unroll
        for (int j = 0; j < 2; j++)
            #pragma unroll
            for (int nn = 0; nn < 8; nn++) acc[j][nn] = 0ULL;

        #pragma unroll 2
        for (int qq = 0; qq < 32; qq++){
            int q = q0 + qq;
            const ulonglong2 xa = *(const ulonglong2*)&sX[r0*II + q*4];
            const ulonglong2 xb = *(const ulonglong2*)&sX[(r0+1)*II + q*4];
            const ulonglong2* Uq = (const ulonglong2*)&sU[q*(NN*4) + nb0*4];
            #pragma unroll
            for (int nn = 0; nn < 8; nn++){
                ulonglong2 u = Uq[nn];
                ffma2(acc[0][nn], xa.x, u.x); ffma2(acc[0][nn], xa.y, u.y);
                ffma2(acc[1][nn], xb.x, u.x); ffma2(acc[1][nn], xb.y, u.y);
            }
        }
        // write K-split partials (padded stride kills conflicts)
        #pragma unroll
        for (int j = 0; j < 2; j++)
            #pragma unroll
            for (int nn = 0; nn < 8; nn++){
                float2 p = unpack2(acc[j][nn]);
                sP[ks*SPSPLIT + (r0+j)*SPS + nb0 + nn] = p.x + p.y;
            }
    }
    __syncthreads();

    // ---- phase 1b: combine 4 K-splits + softmax; each warp 4 rows, lane = n
    {
        int row0 = w*4;
        float rv[4];
        #pragma unroll
        for (int rr = 0; rr < 4; rr++){
            int row = row0 + rr;
            float a = sP[row*SPS + lane]
                    + sP[SPSPLIT + row*SPS + lane]
                    + sP[2*SPSPLIT + row*SPS + lane]
                    + sP[3*SPSPLIT + row*SPS + lane];
            int gidx = ((b*SS) + s0 + row)*NN + lane;
            if (pass_c) a += g_b1[gidx];
            else        g_b1[gidx] = a;
            float m = a;
            #pragma unroll
            for (int off = 16; off > 0; off >>= 1)
                m = fmaxf(m, __shfl_xor_sync(0xffffffffu, m, off));
            float e = __expf(a - m);
            float ssum = e;
            #pragma unroll
            for (int off = 16; off > 0; off >>= 1)
                ssum += __shfl_xor_sync(0xffffffffu, ssum, off);
            rv[rr] = e / ssum;
        }
        __syncthreads();                 // all sP reads done before aliasing writes
        #pragma unroll
        for (int rr = 0; rr < 4; rr++)
            sR[(row0+rr)*NN + lane] = rv[rr];
    }
    __syncthreads();

    // ---- phase 2: yP[n,i] = sum_ts r[ts,n]*x[ts,i]
    // thread: ng=tid>>7 -> n in [8ng,8ng+8); c=tid&127 -> floats [c*4,c*4+4)
    {
        int ng = tid >> 7, c = tid & 127;
        int nb = ng*8;
        ull acc[16];
        #pragma unroll
        for (int p = 0; p < 16; p++) acc[p] = 0ULL;
        for (int ts = 0; ts < TS; ts++){
            const ulonglong2 rA = *(const ulonglong2*)&sR[ts*NN + nb];
            const ulonglong2 rB = *(const ulonglong2*)&sR[ts*NN + nb + 4];
            float2 r01 = unpack2(rA.x), r23 = unpack2(rA.y);
            float2 r45 = unpack2(rB.x), r67 = unpack2(rB.y);
            ull rv0 = pack2(r01.x, r01.x), rv1 = pack2(r01.y, r01.y);
            ull rv2 = pack2(r23.x, r23.x), rv3 = pack2(r23.y, r23.y);
            ull rv4 = pack2(r45.x, r45.x), rv5 = pack2(r45.y, r45.y);
            ull rv6 = pack2(r67.x, r67.x), rv7 = pack2(r67.y, r67.y);
            const ulonglong2 xv = *(const ulonglong2*)&sX[ts*II + c*4];
            ffma2(acc[0],  xv.x, rv0); ffma2(acc[1],  xv.y, rv0);
            ffma2(acc[2],  xv.x, rv1); ffma2(acc[3],  xv.y, rv1);
            ffma2(acc[4],  xv.x, rv2); ffma2(acc[5],  xv.y, rv2);
            ffma2(acc[6],  xv.x, rv3); ffma2(acc[7],  xv.y, rv3);
            ffma2(acc[8],  xv.x, rv4); ffma2(acc[9],  xv.y, rv4);
            ffma2(acc[10], xv.x, rv5); ffma2(acc[11], xv.y, rv5);
            ffma2(acc[12], xv.x, rv6); ffma2(acc[13], xv.y, rv6);
            ffma2(acc[14], xv.x, rv7); ffma2(acc[15], xv.y, rv7);
        }
        // flush per-block y partials (coalesced STG.128)
        #pragma unroll
        for (int j = 0; j < 8; j++){
            float2 p0 = unpack2(acc[2*j]);
            float2 p1 = unpack2(acc[2*j+1]);
            float4 v = {p0.x, p0.y, p1.x, p1.y};
            *(float4*)&g_yP[(((size_t)(b*NN + nb + j))*NTB + blk)*II + c*4] = v;
        }
    }
}

// ------------------------------------------------ launch (8 kernels)
extern "C" void kernel_launch(void* const* d_in, const int* in_sizes, int n_in,
                              void* d_out, int out_size){
    const float* x = (const float*)d_in[0];
    const float* W = (const float*)d_in[1];
    float* out = (float*)d_out;

    const size_t shmem = (size_t)(TS*II + II*NN + 4*SPSPLIT) * sizeof(float); // 231424
    cudaFuncSetAttribute(fused_pass_kernel,
                         cudaFuncAttributeMaxDynamicSharedMemorySize, (int)shmem);

    // it 0: r uniform -> nodes0 from xsum
    xsum_kernel<<<dim3(32, BB), 512>>>(x);                          // #1
    nodesA_kernel<<<dim3(NN, BB), 512>>>(W, 1.0f/32.0f, 1, nullptr);// #2
    nodesB_kernel<<<dim3(NN, 4, BB), 128>>>(W);                     // #3

    // it 1
    fused_pass_kernel<<<dim3(NTB, BB), 512, shmem>>>(x, 0);         // #4 <- ncu target
    nodesA_kernel<<<dim3(NN, BB), 512>>>(W, 1.0f, 0, nullptr);      // #5
    nodesB_kernel<<<dim3(NN, 4, BB), 128>>>(W);                     // #6

    // it 2
    fused_pass_kernel<<<dim3(NTB, BB), 512, shmem>>>(x, 1);         // #7
    nodesA_kernel<<<dim3(NN, BB), 512>>>(W, 1.0f, 0, out);          // #8
}

// round 9
// speedup vs baseline: 1.2980x; 1.2980x over previous
#include <cuda_runtime.h>

// CapsuleLayer: x[8,2048,512], W[32,512,64] -> nodes[8,32,64]
// Fused routing, capsules never materialized:
//   nodes = (sum_s r*x) @ W[n];  agreement = x . (W[n] @ tanh(nodes))

#define BB 8
#define SS 2048
#define II 512
#define NN 32
#define DD 64
#define TS 64            // s-rows per fused block
#define NT (SS/TS)       // 32 tiles per b
#define PP 32            // xsum partial slabs

typedef unsigned long long ull;

__device__ __align__(16) float g_xsumP[PP*BB*II];
__device__ __align__(16) float g_yP[BB*NN*NT*II];   // per-tile y partials
__device__ __align__(16) float g_U[BB*II*NN];       // [b][i>>2][n][i&3]
__device__ float g_b1[BB*SS*NN];

__device__ __forceinline__ void ffma2(ull &d, ull a, ull b){
    asm("fma.rn.f32x2 %0, %1, %2, %0;" : "+l"(d) : "l"(a), "l"(b));
}
__device__ __forceinline__ ull pack2(float lo, float hi){
    ull r; asm("mov.b64 %0, {%1, %2};" : "=l"(r) : "f"(lo), "f"(hi)); return r;
}
__device__ __forceinline__ float2 unpack2(ull v){
    float2 r; asm("mov.b64 {%0, %1}, %2;" : "=f"(r.x), "=f"(r.y) : "l"(v)); return r;
}

// ------------------------------------------------ xsum partials (no atomics)
__global__ void xsum_kernel(const float* __restrict__ x){
    int p = blockIdx.x, b = blockIdx.y, tid = threadIdx.x;   // grid (PP,8), 512 thr
    const float* xp = x + ((size_t)(b*SS + p*(SS/PP)))*II + tid;
    float acc = 0.f;
    #pragma unroll 16
    for (int r = 0; r < SS/PP; r++) acc += xp[(size_t)r*II];
    g_xsumP[(size_t)(p*BB + b)*II + tid] = acc;
}

// ------------------------------------------------ nodes / tanh / U update
// grid (NN, BB), 512 threads. out!=null => final iter, write nodes only.
__global__ void __launch_bounds__(512)
nodes_update_kernel(const float* __restrict__ W, float scale,
                    int use_xsum, float* __restrict__ out){
    int n = blockIdx.x, b = blockIdx.y, tid = threadIdx.x;
    __shared__ float ys[II];
    __shared__ float sPart[32*68];   // padded: stride 68
    __shared__ float tsm[DD];

    // ---- load ys (xsum reduction OR y-partial reduction), high MLP
    if (tid < II){
        float a = 0.f;
        if (use_xsum){
            const float* p0 = g_xsumP + tid;
            #pragma unroll
            for (int p = 0; p < PP; p++) a += p0[(size_t)(p*BB + b)*II];
        } else {
            const float* p0 = g_yP + ((size_t)(b*NN + n)*NT)*II + tid;
            #pragma unroll
            for (int t = 0; t < NT; t++) a += p0[(size_t)t*II];
        }
        ys[tid] = a;
    }
    __syncthreads();

    // ---- part A: nd[d] = sum_i ys[i]*W[n][i][d]; thread = (ch, d4), MLP 16
    {
        int d4 = tid & 15, ch = tid >> 4;           // 16 d-quads x 32 i-chunks
        const float4* Wp = (const float4*)(W + ((size_t)n*II + ch*16)*DD) + d4;
        float4 acc = {0.f,0.f,0.f,0.f};
        #pragma unroll
        for (int j = 0; j < 16; j++){
            float yv = ys[ch*16 + j];
            float4 w = Wp[j*16];
            acc.x += yv*w.x; acc.y += yv*w.y; acc.z += yv*w.z; acc.w += yv*w.w;
        }
        float* sp = &sPart[ch*68 + d4*4];
        sp[0] = acc.x; sp[1] = acc.y; sp[2] = acc.z; sp[3] = acc.w;
    }
    __syncthreads();
    if (tid < DD){
        float nd = 0.f;
        #pragma unroll
        for (int ch = 0; ch < 32; ch++) nd += sPart[ch*68 + tid];
        nd *= scale;
        if (out) out[(size_t)(b*NN + n)*DD + tid] = nd;
        else     tsm[tid] = tanhf(nd);
    }
    __syncthreads();

    // ---- part B: U[b,n,i] = W[n][i][:] . tanh(nd); one i per thread
    if (!out && tid < II){
        int i = tid;
        const float4* Wr = (const float4*)(W + ((size_t)n*II + i)*DD);
        float acc = 0.f;
        #pragma unroll
        for (int d4 = 0; d4 < 16; d4++){
            float4 w = Wr[d4];
            acc += w.x*tsm[4*d4] + w.y*tsm[4*d4+1] + w.z*tsm[4*d4+2] + w.w*tsm[4*d4+3];
        }
        g_U[(size_t)b*(II*NN) + (size_t)(i>>2)*(NN*4) + n*4 + (i&3)] = acc;
    }
}

// ------------------------------------------------ fused routing pass
// a[n] = x.U[n] (+b_prev) -> softmax_n -> yP[tile][n,:] = sum r[n]*x
// grid (NT, BB), 512 threads, 224KB dynamic smem, no atomics.
// Phase 1a: warp = (row-group of 16, K-split of 32 quads); x reads are
// broadcasts (conflict-free), U load amortized over 16 rows.
__global__ void __launch_bounds__(512, 1)
fused_pass_kernel(const float* __restrict__ x, int pass_c){
    extern __shared__ float smem[];
    float* sX = smem;             // TS*II  = 32768 floats (128KB)
    float* sU = sX + TS*II;       // II*NN  = 16384 floats (64KB, quad layout)
    float* sP = sU + II*NN;       // 4*TS*NN = 8192 floats (32KB, K-split partials)
    float* sR = sP;               // aliases sP (guarded by barrier)
    int tile = blockIdx.x, b = blockIdx.y, tid = threadIdx.x;
    int s0 = tile*TS;

    // ---- stage x tile + U (coalesced float4)
    const float* xt = x + ((size_t)(b*SS + s0))*II;
    #pragma unroll
    for (int it = 0; it < TS*II/4/512; it++)
        ((float4*)sX)[it*512 + tid] = ((const float4*)xt)[it*512 + tid];
    const float* Ub = g_U + (size_t)b*(II*NN);
    #pragma unroll
    for (int it = 0; it < II*NN/4/512; it++)
        ((float4*)sU)[it*512 + tid] = ((const float4*)Ub)[it*512 + tid];
    __syncthreads();

    // ---- phase 1a: agreement; warp = (rg rows [16rg,16rg+16), ks quads [32ks,32ks+32))
    {
        int warp = tid >> 5, lane = tid & 31;
        int rg = warp >> 2, ks = warp & 3;
        int row0 = rg*16, q0 = ks*32;
        ull a2[16];
        #pragma unroll
        for (int r = 0; r < 16; r++) a2[r] = 0ULL;
        const ulonglong2* U2 = (const ulonglong2*)sU;   // [q*NN + n] -> 4 floats
        #pragma unroll 2
        for (int qq = 0; qq < 32; qq++){
            int q = q0 + qq;
            ulonglong2 u = U2[q*NN + lane];
            #pragma unroll
            for (int rr = 0; rr < 16; rr++){
                const ulonglong2 xv = *(const ulonglong2*)&sX[(row0+rr)*II + q*4];
                ffma2(a2[rr], xv.x, u.x);
                ffma2(a2[rr], xv.y, u.y);
            }
        }
        #pragma unroll
        for (int rr = 0; rr < 16; rr++){
            float2 p = unpack2(a2[rr]);
            sP[ks*(TS*NN) + (row0+rr)*NN + lane] = p.x + p.y;
        }
    }
    __syncthreads();

    // ---- phase 1b: combine 4 K-splits + softmax; each warp 4 rows, lane = n
    {
        int warp = tid >> 5, lane = tid & 31;
        int row0 = warp*4;
        float rv[4];
        #pragma unroll
        for (int rr = 0; rr < 4; rr++){
            int row = row0 + rr;
            float a = sP[row*NN + lane]
                    + sP[TS*NN + row*NN + lane]
                    + sP[2*TS*NN + row*NN + lane]
                    + sP[3*TS*NN + row*NN + lane];
            int gidx = ((b*SS) + s0 + row)*NN + lane;
            if (pass_c) a += g_b1[gidx];
            else        g_b1[gidx] = a;
            float m = a;
            #pragma unroll
            for (int off = 16; off > 0; off >>= 1)
                m = fmaxf(m, __shfl_xor_sync(0xffffffffu, m, off));
            float e = __expf(a - m);
            float ssum = e;
            #pragma unroll
            for (int off = 16; off > 0; off >>= 1)
                ssum += __shfl_xor_sync(0xffffffffu, ssum, off);
            rv[rr] = e / ssum;
        }
        __syncthreads();             // all sP reads done before aliasing writes
        #pragma unroll
        for (int rr = 0; rr < 4; rr++)
            sR[(row0+rr)*NN + lane] = rv[rr];
    }
    __syncthreads();

    // ---- phase 2: yP[n,i] = sum_ts r[ts,n]*x[ts,i]
    // thread: g2=tid>>7 -> n in [8*g2, 8*g2+8); c=tid&127 -> floats [c*4, c*4+4)
    {
        int g2 = tid >> 7, c = tid & 127;
        int nb = g2*8;
        ull acc[16];
        #pragma unroll
        for (int p = 0; p < 16; p++) acc[p] = 0ULL;
        for (int ts = 0; ts < TS; ts++){
            const ulonglong2 rA = *(const ulonglong2*)&sR[ts*NN + nb];
            const ulonglong2 rB = *(const ulonglong2*)&sR[ts*NN + nb + 4];
            float2 r01 = unpack2(rA.x), r23 = unpack2(rA.y);
            float2 r45 = unpack2(rB.x), r67 = unpack2(rB.y);
            ull rv0 = pack2(r01.x, r01.x), rv1 = pack2(r01.y, r01.y);
            ull rv2 = pack2(r23.x, r23.x), rv3 = pack2(r23.y, r23.y);
            ull rv4 = pack2(r45.x, r45.x), rv5 = pack2(r45.y, r45.y);
            ull rv6 = pack2(r67.x, r67.x), rv7 = pack2(r67.y, r67.y);
            const ulonglong2 xv = *(const ulonglong2*)&sX[ts*II + c*4];
            ffma2(acc[0],  xv.x, rv0); ffma2(acc[1],  xv.y, rv0);
            ffma2(acc[2],  xv.x, rv1); ffma2(acc[3],  xv.y, rv1);
            ffma2(acc[4],  xv.x, rv2); ffma2(acc[5],  xv.y, rv2);
            ffma2(acc[6],  xv.x, rv3); ffma2(acc[7],  xv.y, rv3);
            ffma2(acc[8],  xv.x, rv4); ffma2(acc[9],  xv.y, rv4);
            ffma2(acc[10], xv.x, rv5); ffma2(acc[11], xv.y, rv5);
            ffma2(acc[12], xv.x, rv6); ffma2(acc[13], xv.y, rv6);
            ffma2(acc[14], xv.x, rv7); ffma2(acc[15], xv.y, rv7);
        }
        // flush partials: coalesced STG.128, no atomics
        #pragma unroll
        for (int j = 0; j < 8; j++){
            float2 p0 = unpack2(acc[2*j]);
            float2 p1 = unpack2(acc[2*j+1]);
            float4 v = {p0.x, p0.y, p1.x, p1.y};
            *(float4*)&g_yP[(((size_t)(b*NN + nb + j))*NT + tile)*II + c*4] = v;
        }
    }
}

// ------------------------------------------------ launch (6 kernels)
extern "C" void kernel_launch(void* const* d_in, const int* in_sizes, int n_in,
                              void* d_out, int out_size){
    const float* x = (const float*)d_in[0];
    const float* W = (const float*)d_in[1];
    float* out = (float*)d_out;

    const size_t shmem = (size_t)(TS*II + II*NN + 4*TS*NN) * sizeof(float); // 229376
    cudaFuncSetAttribute(fused_pass_kernel,
                         cudaFuncAttributeMaxDynamicSharedMemorySize, (int)shmem);

    // it 0: r uniform -> nodes0 from xsum
    xsum_kernel<<<dim3(PP, BB), 512>>>(x);
    nodes_update_kernel<<<dim3(NN, BB), 512>>>(W, 1.0f/32.0f, 1, nullptr);

    // it 1
    fused_pass_kernel<<<dim3(NT, BB), 512, shmem>>>(x, 0);
    nodes_update_kernel<<<dim3(NN, BB), 512>>>(W, 1.0f, 0, nullptr);

    // it 2
    fused_pass_kernel<<<dim3(NT, BB), 512, shmem>>>(x, 1);
    nodes_update_kernel<<<dim3(NN, BB), 512>>>(W, 1.0f, 0, out);
}